// round 7
// baseline (speedup 1.0000x reference)
#include <cuda_runtime.h>
#include <cuda_bf16.h>
#include <math.h>

// Problem constants (fixed shapes per reference)
#define NN_MAX 10000
#define EE_MAX 320000
#define C 64

static __device__ float g_y0 [NN_MAX * 64];    // [n][u]
static __device__ float g_y1 [NN_MAX * 192];   // [n][m][u]
static __device__ float g_sc0[NN_MAX * 64];    // [n][v]
static __device__ float g_sc1[NN_MAX * 192];   // [n][m][v]
static __device__ float g_agg[NN_MAX * 512];   // [n][u][8] : {s0,s1,v00,v01,v02,v10,v11,v12}

#define INV_SQRT_C    0.125f            // 1/sqrt(64)
#define SC_NORM       0.0625f           // 1/sqrt(64*4)
#define INV_SQRT_NB   0.3535533905932738f  // 1/sqrt(8)
#define INV_SQRT_H    0.3535533905932738f
#define INV_SQRT3     0.5773502691896258f
#define K_SCALE       0.015625f         // 1/(sqrt(32)*sqrt(128)) = 1/64
#define LOG2F_        0.6931471805599453f

// softplus(x) - log(2), numerically stable
static __device__ __forceinline__ float ssp_m_log2(float x) {
    return fmaxf(x, 0.f) + log1pf(expf(-fabsf(x))) - LOG2F_;
}

// ---------------------------------------------------------------------------
// Kernel 0: zero the aggregation scratch
// ---------------------------------------------------------------------------
__global__ void zero_agg_kernel(int n4) {
    int i = blockIdx.x * blockDim.x + threadIdx.x;
    if (i < n4) {
        float4 z = make_float4(0.f, 0.f, 0.f, 0.f);
        reinterpret_cast<float4*>(g_agg)[i] = z;
    }
}

// ---------------------------------------------------------------------------
// Kernel 1: per-node precompute  y0, y1, sc0, sc1
//   block = 64 threads (thread = output channel v), 8 nodes per block
// ---------------------------------------------------------------------------
__global__ __launch_bounds__(64) void node_kernel(
    const float* __restrict__ nf,     // [N,256]
    const float* __restrict__ attrs,  // [N,4]
    const float* __restrict__ Wl0,    // [64,64]
    const float* __restrict__ Wl1,    // [64,64]
    const float* __restrict__ Wsc0,   // [64,4,64]
    const float* __restrict__ Wsc1,   // [64,4,64]
    int N)
{
    __shared__ float sx0[8][64];
    __shared__ float sx1[8][3][64];
    __shared__ float sat[8][4];

    const int v  = threadIdx.x;
    const int n0 = blockIdx.x * 8;
    const int nn = min(8, N - n0);

    for (int i = 0; i < nn; i++) {
        const float* row = nf + (size_t)(n0 + i) * 256;
        sx0[i][v] = row[v];
        #pragma unroll
        for (int j = 0; j < 3; j++) {
            int c = v + j * 64;          // flat (u,m) index, u=c/3 m=c%3
            sx1[i][c % 3][c / 3] = row[64 + c];
        }
    }
    if (v < 32) {
        int i = v >> 2, a = v & 3;
        if (i < nn) sat[i][a] = attrs[(size_t)(n0 + i) * 4 + a];
    }
    __syncthreads();

    float y0[8], y1[8][3], s0[8], s1[8][3];
    #pragma unroll
    for (int i = 0; i < 8; i++) {
        y0[i] = 0.f; s0[i] = 0.f;
        #pragma unroll
        for (int m = 0; m < 3; m++) { y1[i][m] = 0.f; s1[i][m] = 0.f; }
    }

    for (int u = 0; u < 64; u++) {
        float wl0 = Wl0[u * 64 + v];
        float wl1 = Wl1[u * 64 + v];
        float w0a[4], w1a[4];
        #pragma unroll
        for (int a = 0; a < 4; a++) {
            w0a[a] = Wsc0[(u * 4 + a) * 64 + v];
            w1a[a] = Wsc1[(u * 4 + a) * 64 + v];
        }
        #pragma unroll
        for (int i = 0; i < 8; i++) {
            float a0 = sat[i][0], a1 = sat[i][1], a2 = sat[i][2], a3 = sat[i][3];
            float gg0 = a0 * w0a[0] + a1 * w0a[1] + a2 * w0a[2] + a3 * w0a[3];
            float gg1 = a0 * w1a[0] + a1 * w1a[1] + a2 * w1a[2] + a3 * w1a[3];
            float x0 = sx0[i][u];
            y0[i] += x0 * wl0;
            s0[i] += x0 * gg0;
            #pragma unroll
            for (int m = 0; m < 3; m++) {
                float xm = sx1[i][m][u];
                y1[i][m] += xm * wl1;
                s1[i][m] += xm * gg1;
            }
        }
    }

    for (int i = 0; i < nn; i++) {
        int n = n0 + i;
        g_y0 [(size_t)n * 64 + v] = y0[i] * INV_SQRT_C;
        g_sc0[(size_t)n * 64 + v] = s0[i] * SC_NORM;
        #pragma unroll
        for (int m = 0; m < 3; m++) {
            g_y1 [(size_t)n * 192 + m * 64 + v] = y1[i][m] * INV_SQRT_C;
            g_sc1[(size_t)n * 192 + m * 64 + v] = s1[i][m] * SC_NORM;
        }
    }
}

// ---------------------------------------------------------------------------
// Kernel 2: per-edge message + scatter-add (one warp per edge, grid-stride)
//   lane L handles channels u = L and u = L+32
//   W_fc2 columns register-cached per lane (8 k x 8 cols)
// ---------------------------------------------------------------------------
__global__ __launch_bounds__(128) void edge_kernel(
    const float* __restrict__ eattr,  // [E,4]
    const float* __restrict__ eemb,   // [E,8]
    const int*   __restrict__ eidx,   // [2,E]  row0=dst row1=src
    const float* __restrict__ Wfc1,   // [8,8]
    const float* __restrict__ Wfc2,   // [8,256]
    int E)
{
    __shared__ float sWfc1[64];
    const int tid  = threadIdx.x;
    const int lane = tid & 31;
    if (tid < 64) sWfc1[tid] = Wfc1[tid] * INV_SQRT_NB;

    const int warp   = blockIdx.x * (blockDim.x >> 5) + (tid >> 5);
    const int nwarps = gridDim.x * (blockDim.x >> 5);

    // register-cache W_fc2: columns {u0, 64+u0, 128+u0, 192+u0, u1, 64+u1, 128+u1, 192+u1}
    float W2[8][8];
    {
        const int u0 = lane, u1 = lane + 32;
        int jc[8];
        jc[0] = u0; jc[1] = 64 + u0; jc[2] = 128 + u0; jc[3] = 192 + u0;
        jc[4] = u1; jc[5] = 64 + u1; jc[6] = 128 + u1; jc[7] = 192 + u1;
        #pragma unroll
        for (int k = 0; k < 8; k++)
            #pragma unroll
            for (int c = 0; c < 8; c++)
                W2[k][c] = Wfc2[k * 256 + jc[c]] * INV_SQRT_H;
    }
    __syncthreads();

    for (int e = warp; e < E; e += nwarps) {
        const int dst = eidx[e];
        const int src = eidx[E + e];
        const float4 ea = *reinterpret_cast<const float4*>(eattr + (size_t)e * 4);
        const float sh0  = ea.x;
        const float sh1x = ea.y;
        const float sh1y = ea.z;
        const float sh1z = ea.w;

        // edge embedding row: lane 0 loads 8 floats as two float4, broadcast via shfl
        float emb[8];
        {
            float4 r0, r1;
            if (lane == 0) {
                const float4* ep = reinterpret_cast<const float4*>(eemb + (size_t)e * 8);
                r0 = ep[0]; r1 = ep[1];
            }
            emb[0] = __shfl_sync(0xffffffffu, r0.x, 0);
            emb[1] = __shfl_sync(0xffffffffu, r0.y, 0);
            emb[2] = __shfl_sync(0xffffffffu, r0.z, 0);
            emb[3] = __shfl_sync(0xffffffffu, r0.w, 0);
            emb[4] = __shfl_sync(0xffffffffu, r1.x, 0);
            emb[5] = __shfl_sync(0xffffffffu, r1.y, 0);
            emb[6] = __shfl_sync(0xffffffffu, r1.z, 0);
            emb[7] = __shfl_sync(0xffffffffu, r1.w, 0);
        }

        // radial MLP hidden layer: lanes 0..7 each compute one h_k, then broadcast
        float hk = 0.f;
        if (lane < 8) {
            #pragma unroll
            for (int b = 0; b < 8; b++)
                hk += emb[b] * sWfc1[b * 8 + lane];
            hk = ssp_m_log2(hk);
        }
        float h[8];
        #pragma unroll
        for (int k = 0; k < 8; k++) h[k] = __shfl_sync(0xffffffffu, hk, k);

        // w columns this lane needs (wp1..wp4 for its two channels)
        float w[8];
        #pragma unroll
        for (int c = 0; c < 8; c++) {
            float acc = 0.f;
            #pragma unroll
            for (int k = 0; k < 8; k++) acc += h[k] * W2[k][c];
            w[c] = acc;
        }

        const float* y0p  = g_y0 + (size_t)src * 64;
        const float* y1p  = g_y1 + (size_t)src * 192;
        float*       aggp = g_agg + (size_t)dst * 512;

        #pragma unroll
        for (int half = 0; half < 2; half++) {
            const int u = lane + half * 32;
            const float x0  = y0p[u];
            const float x1x = y1p[u];
            const float x1y = y1p[64 + u];
            const float x1z = y1p[128 + u];
            const float wp1 = w[half * 4 + 0];
            const float wp2 = w[half * 4 + 1];
            const float wp3 = w[half * 4 + 2];
            const float wp4 = w[half * 4 + 3];

            const float dot3 = x1x * sh1x + x1y * sh1y + x1z * sh1z;
            const float s0v = wp1 * x0 * sh0;
            const float s1v = wp4 * dot3 * INV_SQRT3;
            const float a   = wp2 * x0;
            const float v00 = a * sh1x, v01 = a * sh1y, v02 = a * sh1z;
            const float b   = wp3 * sh0;
            const float v10 = b * x1x, v11 = b * x1y, v12 = b * x1z;

            float* p = aggp + u * 8;
            asm volatile("red.global.add.v4.f32 [%0], {%1,%2,%3,%4};"
                         :: "l"(p),     "f"(s0v), "f"(s1v), "f"(v00), "f"(v01) : "memory");
            asm volatile("red.global.add.v4.f32 [%0], {%1,%2,%3,%4};"
                         :: "l"(p + 4), "f"(v02), "f"(v10), "f"(v11), "f"(v12) : "memory");
        }
    }
}

// ---------------------------------------------------------------------------
// Kernel 3: output linears + shortcut
//   block = 256 threads = 4 nodes x 64 channels
// ---------------------------------------------------------------------------
__global__ __launch_bounds__(256) void out_kernel(
    const float* __restrict__ Wl20,   // [128,64]
    const float* __restrict__ Wl21,   // [128,64]
    float* __restrict__ out,          // [N,256]
    int N)
{
    __shared__ float sagg[4][512];
    const int tid = threadIdx.x;
    const int ni  = tid >> 6;
    const int v   = tid & 63;
    const int n   = blockIdx.x * 4 + ni;

    if (n < N) {
        const float4* srcp = reinterpret_cast<const float4*>(g_agg + (size_t)n * 512);
        float4* dstp = reinterpret_cast<float4*>(sagg[ni]);
        dstp[v]      = srcp[v];
        dstp[v + 64] = srcp[v + 64];
    }
    __syncthreads();
    if (n >= N) return;

    float acc0 = g_sc0[(size_t)n * 64 + v];
    float acc1[3];
    #pragma unroll
    for (int m = 0; m < 3; m++) acc1[m] = g_sc1[(size_t)n * 192 + m * 64 + v];

    const float* s = sagg[ni];
    // U in [0,64): s slot 0, v slots 2..4 ; U in [64,128): s slot 1, v slots 5..7
    #pragma unroll 4
    for (int u = 0; u < 64; u++) {
        float wa = Wl20[u * 64 + v] * K_SCALE;
        float wb = Wl21[u * 64 + v] * K_SCALE;
        const float* g = s + u * 8;
        acc0 += g[0] * wa;
        #pragma unroll
        for (int m = 0; m < 3; m++) acc1[m] += g[2 + m] * wb;
    }
    #pragma unroll 4
    for (int u = 0; u < 64; u++) {
        float wa = Wl20[(64 + u) * 64 + v] * K_SCALE;
        float wb = Wl21[(64 + u) * 64 + v] * K_SCALE;
        const float* g = s + u * 8;
        acc0 += g[1] * wa;
        #pragma unroll
        for (int m = 0; m < 3; m++) acc1[m] += g[5 + m] * wb;
    }

    float* orow = out + (size_t)n * 256;
    orow[v] = acc0;
    #pragma unroll
    for (int m = 0; m < 3; m++) orow[64 + v * 3 + m] = acc1[m];
}

// ---------------------------------------------------------------------------
extern "C" void kernel_launch(void* const* d_in, const int* in_sizes, int n_in,
                              void* d_out, int out_size)
{
    const float* node_features  = (const float*)d_in[0];
    const float* node_attrs     = (const float*)d_in[1];
    const float* edge_attrs     = (const float*)d_in[2];
    const float* edge_embedding = (const float*)d_in[3];
    const int*   edge_index     = (const int*)  d_in[4];
    const float* W_lin1_0       = (const float*)d_in[5];
    const float* W_lin1_1       = (const float*)d_in[6];
    const float* W_fc1          = (const float*)d_in[7];
    const float* W_fc2          = (const float*)d_in[8];
    const float* W_lin2_0       = (const float*)d_in[9];
    const float* W_lin2_1       = (const float*)d_in[10];
    const float* W_sc0          = (const float*)d_in[11];
    const float* W_sc1          = (const float*)d_in[12];
    float* out = (float*)d_out;

    const int N = in_sizes[0] / 256;
    const int E = in_sizes[2] / 4;

    // 0) zero scatter target
    {
        int n4 = N * 512 / 4;
        zero_agg_kernel<<<(n4 + 255) / 256, 256>>>(n4);
    }
    // 1) node precompute
    node_kernel<<<(N + 7) / 8, 64>>>(node_features, node_attrs,
                                     W_lin1_0, W_lin1_1, W_sc0, W_sc1, N);
    // 2) edge messages + scatter-add
    edge_kernel<<<1184, 128>>>(edge_attrs, edge_embedding, edge_index,
                               W_fc1, W_fc2, E);
    // 3) output
    out_kernel<<<(N + 3) / 4, 256>>>(W_lin2_0, W_lin2_1, out, N);
}

// round 8
// speedup vs baseline: 1.0127x; 1.0127x over previous
#include <cuda_runtime.h>
#include <cuda_bf16.h>
#include <math.h>

// Problem constants (fixed shapes per reference)
#define NN_MAX 10000
#define EE_MAX 320000
#define C 64

static __device__ float g_ypack[NN_MAX * 256]; // [n][u][4] : {y0, y1x, y1y, y1z}
static __device__ float g_sc0[NN_MAX * 64];    // [n][v]
static __device__ float g_sc1[NN_MAX * 192];   // [n][m][v]
static __device__ float g_agg[NN_MAX * 512];   // [n][u][8] : {s0,s1,v00,v01,v02,v10,v11,v12}

#define INV_SQRT_C    0.125f            // 1/sqrt(64)
#define SC_NORM       0.0625f           // 1/sqrt(64*4)
#define INV_SQRT_NB   0.3535533905932738f  // 1/sqrt(8)
#define INV_SQRT_H    0.3535533905932738f
#define INV_SQRT3     0.5773502691896258f
#define K_SCALE       0.015625f         // 1/(sqrt(32)*sqrt(128)) = 1/64
#define LOG2F_        0.6931471805599453f

// softplus(x) - log(2), numerically stable
static __device__ __forceinline__ float ssp_m_log2(float x) {
    return fmaxf(x, 0.f) + log1pf(expf(-fabsf(x))) - LOG2F_;
}

// ---------------------------------------------------------------------------
// Kernel 0: zero the aggregation scratch
// ---------------------------------------------------------------------------
__global__ void zero_agg_kernel(int n4) {
    int i = blockIdx.x * blockDim.x + threadIdx.x;
    if (i < n4) {
        float4 z = make_float4(0.f, 0.f, 0.f, 0.f);
        reinterpret_cast<float4*>(g_agg)[i] = z;
    }
}

// ---------------------------------------------------------------------------
// Kernel 1: per-node precompute  y (packed), sc0, sc1
//   block = 64 threads (thread = output channel v), 8 nodes per block
// ---------------------------------------------------------------------------
__global__ __launch_bounds__(64) void node_kernel(
    const float* __restrict__ nf,     // [N,256]
    const float* __restrict__ attrs,  // [N,4]
    const float* __restrict__ Wl0,    // [64,64]
    const float* __restrict__ Wl1,    // [64,64]
    const float* __restrict__ Wsc0,   // [64,4,64]
    const float* __restrict__ Wsc1,   // [64,4,64]
    int N)
{
    __shared__ float sx0[8][64];
    __shared__ float sx1[8][3][64];
    __shared__ float sat[8][4];

    const int v  = threadIdx.x;
    const int n0 = blockIdx.x * 8;
    const int nn = min(8, N - n0);

    for (int i = 0; i < nn; i++) {
        const float* row = nf + (size_t)(n0 + i) * 256;
        sx0[i][v] = row[v];
        #pragma unroll
        for (int j = 0; j < 3; j++) {
            int c = v + j * 64;          // flat (u,m) index, u=c/3 m=c%3
            sx1[i][c % 3][c / 3] = row[64 + c];
        }
    }
    if (v < 32) {
        int i = v >> 2, a = v & 3;
        if (i < nn) sat[i][a] = attrs[(size_t)(n0 + i) * 4 + a];
    }
    __syncthreads();

    float y0[8], y1[8][3], s0[8], s1[8][3];
    #pragma unroll
    for (int i = 0; i < 8; i++) {
        y0[i] = 0.f; s0[i] = 0.f;
        #pragma unroll
        for (int m = 0; m < 3; m++) { y1[i][m] = 0.f; s1[i][m] = 0.f; }
    }

    for (int u = 0; u < 64; u++) {
        float wl0 = Wl0[u * 64 + v];
        float wl1 = Wl1[u * 64 + v];
        float w0a[4], w1a[4];
        #pragma unroll
        for (int a = 0; a < 4; a++) {
            w0a[a] = Wsc0[(u * 4 + a) * 64 + v];
            w1a[a] = Wsc1[(u * 4 + a) * 64 + v];
        }
        #pragma unroll
        for (int i = 0; i < 8; i++) {
            float a0 = sat[i][0], a1 = sat[i][1], a2 = sat[i][2], a3 = sat[i][3];
            float gg0 = a0 * w0a[0] + a1 * w0a[1] + a2 * w0a[2] + a3 * w0a[3];
            float gg1 = a0 * w1a[0] + a1 * w1a[1] + a2 * w1a[2] + a3 * w1a[3];
            float x0 = sx0[i][u];
            y0[i] += x0 * wl0;
            s0[i] += x0 * gg0;
            #pragma unroll
            for (int m = 0; m < 3; m++) {
                float xm = sx1[i][m][u];
                y1[i][m] += xm * wl1;
                s1[i][m] += xm * gg1;
            }
        }
    }

    for (int i = 0; i < nn; i++) {
        int n = n0 + i;
        float4 yv = make_float4(y0[i] * INV_SQRT_C,
                                y1[i][0] * INV_SQRT_C,
                                y1[i][1] * INV_SQRT_C,
                                y1[i][2] * INV_SQRT_C);
        *reinterpret_cast<float4*>(g_ypack + (size_t)n * 256 + v * 4) = yv;
        g_sc0[(size_t)n * 64 + v] = s0[i] * SC_NORM;
        #pragma unroll
        for (int m = 0; m < 3; m++)
            g_sc1[(size_t)n * 192 + m * 64 + v] = s1[i][m] * SC_NORM;
    }
}

// ---------------------------------------------------------------------------
// Kernel 2: per-edge message + scatter-add (one warp per edge, grid-stride)
//   lane L handles channels u = L and u = L+32
//   gather: one LDG.128 per lane per half (packed y layout)
// ---------------------------------------------------------------------------
__global__ __launch_bounds__(128) void edge_kernel(
    const float* __restrict__ eattr,  // [E,4]
    const float* __restrict__ eemb,   // [E,8]
    const int*   __restrict__ eidx,   // [2,E]  row0=dst row1=src
    const float* __restrict__ Wfc1,   // [8,8]
    const float* __restrict__ Wfc2,   // [8,256]
    int E)
{
    __shared__ float sWfc1[64];
    const int tid  = threadIdx.x;
    const int lane = tid & 31;
    if (tid < 64) sWfc1[tid] = Wfc1[tid] * INV_SQRT_NB;

    const int warp   = blockIdx.x * (blockDim.x >> 5) + (tid >> 5);
    const int nwarps = gridDim.x * (blockDim.x >> 5);

    // register-cache W_fc2: columns {u0, 64+u0, 128+u0, 192+u0, u1, 64+u1, 128+u1, 192+u1}
    float W2[8][8];
    {
        const int u0 = lane, u1 = lane + 32;
        int jc[8];
        jc[0] = u0; jc[1] = 64 + u0; jc[2] = 128 + u0; jc[3] = 192 + u0;
        jc[4] = u1; jc[5] = 64 + u1; jc[6] = 128 + u1; jc[7] = 192 + u1;
        #pragma unroll
        for (int k = 0; k < 8; k++)
            #pragma unroll
            for (int c = 0; c < 8; c++)
                W2[k][c] = Wfc2[k * 256 + jc[c]] * INV_SQRT_H;
    }
    __syncthreads();

    for (int e = warp; e < E; e += nwarps) {
        const int dst = eidx[e];
        const int src = eidx[E + e];
        const float4 ea = *reinterpret_cast<const float4*>(eattr + (size_t)e * 4);
        const float sh0  = ea.x;
        const float sh1x = ea.y;
        const float sh1y = ea.z;
        const float sh1z = ea.w;

        // edge embedding row: lane 0 loads 8 floats as two float4, broadcast via shfl
        float emb[8];
        {
            float4 r0, r1;
            if (lane == 0) {
                const float4* ep = reinterpret_cast<const float4*>(eemb + (size_t)e * 8);
                r0 = ep[0]; r1 = ep[1];
            }
            emb[0] = __shfl_sync(0xffffffffu, r0.x, 0);
            emb[1] = __shfl_sync(0xffffffffu, r0.y, 0);
            emb[2] = __shfl_sync(0xffffffffu, r0.z, 0);
            emb[3] = __shfl_sync(0xffffffffu, r0.w, 0);
            emb[4] = __shfl_sync(0xffffffffu, r1.x, 0);
            emb[5] = __shfl_sync(0xffffffffu, r1.y, 0);
            emb[6] = __shfl_sync(0xffffffffu, r1.z, 0);
            emb[7] = __shfl_sync(0xffffffffu, r1.w, 0);
        }

        // radial MLP hidden layer: lanes 0..7 each compute one h_k, then broadcast
        float hk = 0.f;
        if (lane < 8) {
            #pragma unroll
            for (int b = 0; b < 8; b++)
                hk += emb[b] * sWfc1[b * 8 + lane];
            hk = ssp_m_log2(hk);
        }
        float h[8];
        #pragma unroll
        for (int k = 0; k < 8; k++) h[k] = __shfl_sync(0xffffffffu, hk, k);

        // w columns this lane needs (wp1..wp4 for its two channels)
        float w[8];
        #pragma unroll
        for (int c = 0; c < 8; c++) {
            float acc = 0.f;
            #pragma unroll
            for (int k = 0; k < 8; k++) acc += h[k] * W2[k][c];
            w[c] = acc;
        }

        const float* yp   = g_ypack + (size_t)src * 256;
        float*       aggp = g_agg   + (size_t)dst * 512;

        #pragma unroll
        for (int half = 0; half < 2; half++) {
            const int u = lane + half * 32;
            const float4 y = *reinterpret_cast<const float4*>(yp + u * 4);
            const float x0  = y.x;
            const float x1x = y.y;
            const float x1y = y.z;
            const float x1z = y.w;
            const float wp1 = w[half * 4 + 0];
            const float wp2 = w[half * 4 + 1];
            const float wp3 = w[half * 4 + 2];
            const float wp4 = w[half * 4 + 3];

            const float dot3 = x1x * sh1x + x1y * sh1y + x1z * sh1z;
            const float s0v = wp1 * x0 * sh0;
            const float s1v = wp4 * dot3 * INV_SQRT3;
            const float a   = wp2 * x0;
            const float v00 = a * sh1x, v01 = a * sh1y, v02 = a * sh1z;
            const float b   = wp3 * sh0;
            const float v10 = b * x1x, v11 = b * x1y, v12 = b * x1z;

            float* p = aggp + u * 8;
            asm volatile("red.global.add.v4.f32 [%0], {%1,%2,%3,%4};"
                         :: "l"(p),     "f"(s0v), "f"(s1v), "f"(v00), "f"(v01) : "memory");
            asm volatile("red.global.add.v4.f32 [%0], {%1,%2,%3,%4};"
                         :: "l"(p + 4), "f"(v02), "f"(v10), "f"(v11), "f"(v12) : "memory");
        }
    }
}

// ---------------------------------------------------------------------------
// Kernel 3: output linears + shortcut
//   block = 256 threads, 16 nodes per block, 4 nodes per thread
//   thread (ni = tid>>6, v = tid&63) handles nodes n0 + ni + 4j, j=0..3
//   one u-loop covers both U halves via two float4 shared reads per node
// ---------------------------------------------------------------------------
__global__ __launch_bounds__(256) void out_kernel(
    const float* __restrict__ Wl20,   // [128,64]
    const float* __restrict__ Wl21,   // [128,64]
    float* __restrict__ out,          // [N,256]
    int N)
{
    __shared__ float sagg[16][512];
    const int tid = threadIdx.x;
    const int ni  = tid >> 6;
    const int v   = tid & 63;
    const int n0  = blockIdx.x * 16;

    // stage up to 16 nodes of agg (128 float4 per node)
    {
        const float4* srcp = reinterpret_cast<const float4*>(g_agg + (size_t)n0 * 512);
        float4* dstp = reinterpret_cast<float4*>(&sagg[0][0]);
        const int avail = min(16, N - n0) * 128;
        for (int i = tid; i < avail; i += 256)
            dstp[i] = srcp[i];
    }
    __syncthreads();

    float acc0[4], acc1[4][3];
    #pragma unroll
    for (int j = 0; j < 4; j++) {
        const int n = n0 + ni + 4 * j;
        if (n < N) {
            acc0[j] = g_sc0[(size_t)n * 64 + v];
            #pragma unroll
            for (int m = 0; m < 3; m++)
                acc1[j][m] = g_sc1[(size_t)n * 192 + m * 64 + v];
        } else {
            acc0[j] = 0.f;
            #pragma unroll
            for (int m = 0; m < 3; m++) acc1[j][m] = 0.f;
        }
    }

    #pragma unroll 2
    for (int u = 0; u < 64; u++) {
        const float waL = Wl20[u * 64 + v]        * K_SCALE;   // U = u
        const float waH = Wl20[(64 + u) * 64 + v] * K_SCALE;   // U = 64+u
        const float wbL = Wl21[u * 64 + v]        * K_SCALE;
        const float wbH = Wl21[(64 + u) * 64 + v] * K_SCALE;
        #pragma unroll
        for (int j = 0; j < 4; j++) {
            const float* g = &sagg[ni + 4 * j][u * 8];
            const float4 gA = *reinterpret_cast<const float4*>(g);     // {s0,s1,v00,v01}
            const float4 gB = *reinterpret_cast<const float4*>(g + 4); // {v02,v10,v11,v12}
            acc0[j]    += gA.x * waL + gA.y * waH;
            acc1[j][0] += gA.z * wbL + gB.y * wbH;
            acc1[j][1] += gA.w * wbL + gB.z * wbH;
            acc1[j][2] += gB.x * wbL + gB.w * wbH;
        }
    }

    #pragma unroll
    for (int j = 0; j < 4; j++) {
        const int n = n0 + ni + 4 * j;
        if (n < N) {
            float* orow = out + (size_t)n * 256;
            orow[v] = acc0[j];
            #pragma unroll
            for (int m = 0; m < 3; m++)
                orow[64 + v * 3 + m] = acc1[j][m];
        }
    }
}

// ---------------------------------------------------------------------------
extern "C" void kernel_launch(void* const* d_in, const int* in_sizes, int n_in,
                              void* d_out, int out_size)
{
    const float* node_features  = (const float*)d_in[0];
    const float* node_attrs     = (const float*)d_in[1];
    const float* edge_attrs     = (const float*)d_in[2];
    const float* edge_embedding = (const float*)d_in[3];
    const int*   edge_index     = (const int*)  d_in[4];
    const float* W_lin1_0       = (const float*)d_in[5];
    const float* W_lin1_1       = (const float*)d_in[6];
    const float* W_fc1          = (const float*)d_in[7];
    const float* W_fc2          = (const float*)d_in[8];
    const float* W_lin2_0       = (const float*)d_in[9];
    const float* W_lin2_1       = (const float*)d_in[10];
    const float* W_sc0          = (const float*)d_in[11];
    const float* W_sc1          = (const float*)d_in[12];
    float* out = (float*)d_out;

    const int N = in_sizes[0] / 256;
    const int E = in_sizes[2] / 4;

    // 0) zero scatter target
    {
        int n4 = N * 512 / 4;
        zero_agg_kernel<<<(n4 + 255) / 256, 256>>>(n4);
    }
    // 1) node precompute
    node_kernel<<<(N + 7) / 8, 64>>>(node_features, node_attrs,
                                     W_lin1_0, W_lin1_1, W_sc0, W_sc1, N);
    // 2) edge messages + scatter-add
    edge_kernel<<<1184, 128>>>(edge_attrs, edge_embedding, edge_index,
                               W_fc1, W_fc2, E);
    // 3) output
    out_kernel<<<(N + 15) / 16, 256>>>(W_lin2_0, W_lin2_1, out, N);
}

// round 9
// speedup vs baseline: 1.1439x; 1.1296x over previous
#include <cuda_runtime.h>
#include <cuda_bf16.h>
#include <math.h>

// Problem constants (fixed shapes per reference)
#define NN_MAX 10000
#define EE_MAX 320000
#define C 64

static __device__ float g_ypack[NN_MAX * 256]; // [n][u][4] : {y0, y1x, y1y, y1z}
static __device__ float g_sc0[NN_MAX * 64];    // [n][v]
static __device__ float g_sc1[NN_MAX * 192];   // [n][m][v]
static __device__ float g_agg[NN_MAX * 512];   // [n][u][8] : {s0,s1,v00,v01,v02,v10,v11,v12}

// CSR sort scratch
static __device__ int g_count [NN_MAX];        // per-dst edge count
static __device__ int g_offset[NN_MAX + 1];    // exclusive prefix
static __device__ int g_cursor[NN_MAX];        // scatter cursors
static __device__ int g_perm  [EE_MAX];        // edge ids sorted by dst

#define INV_SQRT_C    0.125f            // 1/sqrt(64)
#define SC_NORM       0.0625f           // 1/sqrt(64*4)
#define INV_SQRT_NB   0.3535533905932738f  // 1/sqrt(8)
#define INV_SQRT_H    0.3535533905932738f
#define INV_SQRT3     0.5773502691896258f
#define K_SCALE       0.015625f         // 1/(sqrt(32)*sqrt(128)) = 1/64
#define LOG2F_        0.6931471805599453f

// softplus(x) - log(2), numerically stable
static __device__ __forceinline__ float ssp_m_log2(float x) {
    return fmaxf(x, 0.f) + log1pf(expf(-fabsf(x))) - LOG2F_;
}

// ---------------------------------------------------------------------------
// Sort kernel A: zero the per-dst counters
// ---------------------------------------------------------------------------
__global__ void zero_count_kernel(int N) {
    int i = blockIdx.x * blockDim.x + threadIdx.x;
    if (i < N) g_count[i] = 0;
}

// ---------------------------------------------------------------------------
// Sort kernel B: histogram of dst
// ---------------------------------------------------------------------------
__global__ void hist_kernel(const int* __restrict__ eidx, int E) {
    int e = blockIdx.x * blockDim.x + threadIdx.x;
    if (e < E) atomicAdd(&g_count[eidx[e]], 1);
}

// ---------------------------------------------------------------------------
// Sort kernel C: single-block exclusive scan over N counts (N <= 10240)
// ---------------------------------------------------------------------------
__global__ __launch_bounds__(1024) void scan_kernel(int N) {
    __shared__ int ssum[1024];
    const int tid = threadIdx.x;
    const int per = (N + 1023) / 1024;
    const int base = tid * per;

    int s = 0;
    for (int j = 0; j < per; j++) {
        int idx = base + j;
        if (idx < N) s += g_count[idx];
    }
    ssum[tid] = s;
    __syncthreads();
    // Hillis-Steele inclusive scan
    for (int off = 1; off < 1024; off <<= 1) {
        int v = (tid >= off) ? ssum[tid - off] : 0;
        __syncthreads();
        ssum[tid] += v;
        __syncthreads();
    }
    int run = (tid == 0) ? 0 : ssum[tid - 1];
    for (int j = 0; j < per; j++) {
        int idx = base + j;
        if (idx < N) {
            g_offset[idx] = run;
            g_cursor[idx] = run;
            run += g_count[idx];
        }
    }
    if (tid == 1023) g_offset[N] = ssum[1023];
}

// ---------------------------------------------------------------------------
// Sort kernel D: scatter edge ids into dst-sorted order
// ---------------------------------------------------------------------------
__global__ void scatter_kernel(const int* __restrict__ eidx, int E) {
    int e = blockIdx.x * blockDim.x + threadIdx.x;
    if (e < E) {
        int d = eidx[e];
        int pos = atomicAdd(&g_cursor[d], 1);
        g_perm[pos] = e;
    }
}

// ---------------------------------------------------------------------------
// Kernel 1: per-node precompute  y (packed), sc0, sc1
//   block = 64 threads (thread = output channel v), 8 nodes per block
// ---------------------------------------------------------------------------
__global__ __launch_bounds__(64) void node_kernel(
    const float* __restrict__ nf,     // [N,256]
    const float* __restrict__ attrs,  // [N,4]
    const float* __restrict__ Wl0,    // [64,64]
    const float* __restrict__ Wl1,    // [64,64]
    const float* __restrict__ Wsc0,   // [64,4,64]
    const float* __restrict__ Wsc1,   // [64,4,64]
    int N)
{
    __shared__ float sx0[8][64];
    __shared__ float sx1[8][3][64];
    __shared__ float sat[8][4];

    const int v  = threadIdx.x;
    const int n0 = blockIdx.x * 8;
    const int nn = min(8, N - n0);

    for (int i = 0; i < nn; i++) {
        const float* row = nf + (size_t)(n0 + i) * 256;
        sx0[i][v] = row[v];
        #pragma unroll
        for (int j = 0; j < 3; j++) {
            int c = v + j * 64;          // flat (u,m) index, u=c/3 m=c%3
            sx1[i][c % 3][c / 3] = row[64 + c];
        }
    }
    if (v < 32) {
        int i = v >> 2, a = v & 3;
        if (i < nn) sat[i][a] = attrs[(size_t)(n0 + i) * 4 + a];
    }
    __syncthreads();

    float y0[8], y1[8][3], s0[8], s1[8][3];
    #pragma unroll
    for (int i = 0; i < 8; i++) {
        y0[i] = 0.f; s0[i] = 0.f;
        #pragma unroll
        for (int m = 0; m < 3; m++) { y1[i][m] = 0.f; s1[i][m] = 0.f; }
    }

    for (int u = 0; u < 64; u++) {
        float wl0 = Wl0[u * 64 + v];
        float wl1 = Wl1[u * 64 + v];
        float w0a[4], w1a[4];
        #pragma unroll
        for (int a = 0; a < 4; a++) {
            w0a[a] = Wsc0[(u * 4 + a) * 64 + v];
            w1a[a] = Wsc1[(u * 4 + a) * 64 + v];
        }
        #pragma unroll
        for (int i = 0; i < 8; i++) {
            float a0 = sat[i][0], a1 = sat[i][1], a2 = sat[i][2], a3 = sat[i][3];
            float gg0 = a0 * w0a[0] + a1 * w0a[1] + a2 * w0a[2] + a3 * w0a[3];
            float gg1 = a0 * w1a[0] + a1 * w1a[1] + a2 * w1a[2] + a3 * w1a[3];
            float x0 = sx0[i][u];
            y0[i] += x0 * wl0;
            s0[i] += x0 * gg0;
            #pragma unroll
            for (int m = 0; m < 3; m++) {
                float xm = sx1[i][m][u];
                y1[i][m] += xm * wl1;
                s1[i][m] += xm * gg1;
            }
        }
    }

    for (int i = 0; i < nn; i++) {
        int n = n0 + i;
        float4 yv = make_float4(y0[i] * INV_SQRT_C,
                                y1[i][0] * INV_SQRT_C,
                                y1[i][1] * INV_SQRT_C,
                                y1[i][2] * INV_SQRT_C);
        *reinterpret_cast<float4*>(g_ypack + (size_t)n * 256 + v * 4) = yv;
        g_sc0[(size_t)n * 64 + v] = s0[i] * SC_NORM;
        #pragma unroll
        for (int m = 0; m < 3; m++)
            g_sc1[(size_t)n * 192 + m * 64 + v] = s1[i][m] * SC_NORM;
    }
}

// ---------------------------------------------------------------------------
// Kernel 2: CSR edge aggregation — one warp per dst node, NO atomics.
//   lane L handles channels u = L and u = L+32 (16 register accumulators)
//   W_fc2 columns register-cached per lane
// ---------------------------------------------------------------------------
__global__ __launch_bounds__(128) void edge_csr_kernel(
    const float* __restrict__ eattr,  // [E,4]
    const float* __restrict__ eemb,   // [E,8]
    const int*   __restrict__ eidx,   // [2,E]  row0=dst row1=src
    const float* __restrict__ Wfc1,   // [8,8]
    const float* __restrict__ Wfc2,   // [8,256]
    int E, int N)
{
    __shared__ float sWfc1[64];
    const int tid  = threadIdx.x;
    const int lane = tid & 31;
    if (tid < 64) sWfc1[tid] = Wfc1[tid] * INV_SQRT_NB;

    // register-cache W_fc2: columns {u0, 64+u0, 128+u0, 192+u0, u1, 64+u1, 128+u1, 192+u1}
    float W2[8][8];
    {
        const int u0 = lane, u1 = lane + 32;
        int jc[8];
        jc[0] = u0; jc[1] = 64 + u0; jc[2] = 128 + u0; jc[3] = 192 + u0;
        jc[4] = u1; jc[5] = 64 + u1; jc[6] = 128 + u1; jc[7] = 192 + u1;
        #pragma unroll
        for (int k = 0; k < 8; k++)
            #pragma unroll
            for (int c = 0; c < 8; c++)
                W2[k][c] = Wfc2[k * 256 + jc[c]] * INV_SQRT_H;
    }
    __syncthreads();

    const int node = blockIdx.x * 4 + (tid >> 5);
    if (node >= N) return;

    const int start = g_offset[node];
    const int end   = g_offset[node + 1];

    float acc[2][8];
    #pragma unroll
    for (int h2 = 0; h2 < 2; h2++)
        #pragma unroll
        for (int c = 0; c < 8; c++) acc[h2][c] = 0.f;

    // prefetch first edge's id + src
    int e_nxt = 0, src_nxt = 0;
    if (start < end) {
        e_nxt   = g_perm[start];
        src_nxt = eidx[E + e_nxt];
    }

    for (int i = start; i < end; i++) {
        const int e   = e_nxt;
        const int src = src_nxt;
        if (i + 1 < end) {                     // prefetch next edge
            e_nxt   = g_perm[i + 1];
            src_nxt = eidx[E + e_nxt];
        }

        const float4 ea = *reinterpret_cast<const float4*>(eattr + (size_t)e * 4);
        const float sh0  = ea.x;
        const float sh1x = ea.y;
        const float sh1y = ea.z;
        const float sh1z = ea.w;

        // edge embedding: lane 0 loads two float4, broadcast via shfl
        float emb[8];
        {
            float4 r0, r1;
            if (lane == 0) {
                const float4* ep = reinterpret_cast<const float4*>(eemb + (size_t)e * 8);
                r0 = ep[0]; r1 = ep[1];
            }
            emb[0] = __shfl_sync(0xffffffffu, r0.x, 0);
            emb[1] = __shfl_sync(0xffffffffu, r0.y, 0);
            emb[2] = __shfl_sync(0xffffffffu, r0.z, 0);
            emb[3] = __shfl_sync(0xffffffffu, r0.w, 0);
            emb[4] = __shfl_sync(0xffffffffu, r1.x, 0);
            emb[5] = __shfl_sync(0xffffffffu, r1.y, 0);
            emb[6] = __shfl_sync(0xffffffffu, r1.z, 0);
            emb[7] = __shfl_sync(0xffffffffu, r1.w, 0);
        }

        // radial MLP hidden layer: lanes 0..7 each compute one h_k, then broadcast
        float hk = 0.f;
        if (lane < 8) {
            #pragma unroll
            for (int b = 0; b < 8; b++)
                hk += emb[b] * sWfc1[b * 8 + lane];
            hk = ssp_m_log2(hk);
        }
        float h[8];
        #pragma unroll
        for (int k = 0; k < 8; k++) h[k] = __shfl_sync(0xffffffffu, hk, k);

        // w columns this lane needs (wp1..wp4 for its two channels)
        float w[8];
        #pragma unroll
        for (int c = 0; c < 8; c++) {
            float a2 = 0.f;
            #pragma unroll
            for (int k = 0; k < 8; k++) a2 += h[k] * W2[k][c];
            w[c] = a2;
        }

        const float* yp = g_ypack + (size_t)src * 256;

        #pragma unroll
        for (int half = 0; half < 2; half++) {
            const int u = lane + half * 32;
            const float4 y = *reinterpret_cast<const float4*>(yp + u * 4);
            const float x0  = y.x;
            const float x1x = y.y;
            const float x1y = y.z;
            const float x1z = y.w;
            const float wp1 = w[half * 4 + 0];
            const float wp2 = w[half * 4 + 1];
            const float wp3 = w[half * 4 + 2];
            const float wp4 = w[half * 4 + 3];

            const float dot3 = x1x * sh1x + x1y * sh1y + x1z * sh1z;
            acc[half][0] += wp1 * x0 * sh0;                  // s0
            acc[half][1] += wp4 * dot3 * INV_SQRT3;          // s1
            const float a = wp2 * x0;
            acc[half][2] += a * sh1x;                        // v00
            acc[half][3] += a * sh1y;                        // v01
            acc[half][4] += a * sh1z;                        // v02
            const float b = wp3 * sh0;
            acc[half][5] += b * x1x;                         // v10
            acc[half][6] += b * x1y;                         // v11
            acc[half][7] += b * x1z;                         // v12
        }
    }

    // write agg row once (plain stores — every node covered by exactly one warp)
    float* aggp = g_agg + (size_t)node * 512;
    #pragma unroll
    for (int half = 0; half < 2; half++) {
        const int u = lane + half * 32;
        float4 w0 = make_float4(acc[half][0], acc[half][1], acc[half][2], acc[half][3]);
        float4 w1 = make_float4(acc[half][4], acc[half][5], acc[half][6], acc[half][7]);
        *reinterpret_cast<float4*>(aggp + u * 8)     = w0;
        *reinterpret_cast<float4*>(aggp + u * 8 + 4) = w1;
    }
}

// ---------------------------------------------------------------------------
// Kernel 3: output linears + shortcut
//   block = 256 threads, 16 nodes per block, 4 nodes per thread
// ---------------------------------------------------------------------------
__global__ __launch_bounds__(256) void out_kernel(
    const float* __restrict__ Wl20,   // [128,64]
    const float* __restrict__ Wl21,   // [128,64]
    float* __restrict__ out,          // [N,256]
    int N)
{
    __shared__ float sagg[16][512];
    const int tid = threadIdx.x;
    const int ni  = tid >> 6;
    const int v   = tid & 63;
    const int n0  = blockIdx.x * 16;

    // stage up to 16 nodes of agg (128 float4 per node)
    {
        const float4* srcp = reinterpret_cast<const float4*>(g_agg + (size_t)n0 * 512);
        float4* dstp = reinterpret_cast<float4*>(&sagg[0][0]);
        const int avail = min(16, N - n0) * 128;
        for (int i = tid; i < avail; i += 256)
            dstp[i] = srcp[i];
    }
    __syncthreads();

    float acc0[4], acc1[4][3];
    #pragma unroll
    for (int j = 0; j < 4; j++) {
        const int n = n0 + ni + 4 * j;
        if (n < N) {
            acc0[j] = g_sc0[(size_t)n * 64 + v];
            #pragma unroll
            for (int m = 0; m < 3; m++)
                acc1[j][m] = g_sc1[(size_t)n * 192 + m * 64 + v];
        } else {
            acc0[j] = 0.f;
            #pragma unroll
            for (int m = 0; m < 3; m++) acc1[j][m] = 0.f;
        }
    }

    #pragma unroll 2
    for (int u = 0; u < 64; u++) {
        const float waL = Wl20[u * 64 + v]        * K_SCALE;   // U = u
        const float waH = Wl20[(64 + u) * 64 + v] * K_SCALE;   // U = 64+u
        const float wbL = Wl21[u * 64 + v]        * K_SCALE;
        const float wbH = Wl21[(64 + u) * 64 + v] * K_SCALE;
        #pragma unroll
        for (int j = 0; j < 4; j++) {
            const float* g = &sagg[ni + 4 * j][u * 8];
            const float4 gA = *reinterpret_cast<const float4*>(g);     // {s0,s1,v00,v01}
            const float4 gB = *reinterpret_cast<const float4*>(g + 4); // {v02,v10,v11,v12}
            acc0[j]    += gA.x * waL + gA.y * waH;
            acc1[j][0] += gA.z * wbL + gB.y * wbH;
            acc1[j][1] += gA.w * wbL + gB.z * wbH;
            acc1[j][2] += gB.x * wbL + gB.w * wbH;
        }
    }

    #pragma unroll
    for (int j = 0; j < 4; j++) {
        const int n = n0 + ni + 4 * j;
        if (n < N) {
            float* orow = out + (size_t)n * 256;
            orow[v] = acc0[j];
            #pragma unroll
            for (int m = 0; m < 3; m++)
                orow[64 + v * 3 + m] = acc1[j][m];
        }
    }
}

// ---------------------------------------------------------------------------
extern "C" void kernel_launch(void* const* d_in, const int* in_sizes, int n_in,
                              void* d_out, int out_size)
{
    const float* node_features  = (const float*)d_in[0];
    const float* node_attrs     = (const float*)d_in[1];
    const float* edge_attrs     = (const float*)d_in[2];
    const float* edge_embedding = (const float*)d_in[3];
    const int*   edge_index     = (const int*)  d_in[4];
    const float* W_lin1_0       = (const float*)d_in[5];
    const float* W_lin1_1       = (const float*)d_in[6];
    const float* W_fc1          = (const float*)d_in[7];
    const float* W_fc2          = (const float*)d_in[8];
    const float* W_lin2_0       = (const float*)d_in[9];
    const float* W_lin2_1       = (const float*)d_in[10];
    const float* W_sc0          = (const float*)d_in[11];
    const float* W_sc1          = (const float*)d_in[12];
    float* out = (float*)d_out;

    const int N = in_sizes[0] / 256;
    const int E = in_sizes[2] / 4;

    // --- CSR sort of edges by dst ---
    zero_count_kernel<<<(N + 255) / 256, 256>>>(N);
    hist_kernel<<<(E + 255) / 256, 256>>>(edge_index, E);
    scan_kernel<<<1, 1024>>>(N);
    scatter_kernel<<<(E + 255) / 256, 256>>>(edge_index, E);

    // --- node precompute (independent of sort) ---
    node_kernel<<<(N + 7) / 8, 64>>>(node_features, node_attrs,
                                     W_lin1_0, W_lin1_1, W_sc0, W_sc1, N);

    // --- edge aggregation, warp per node, no atomics ---
    edge_csr_kernel<<<(N + 3) / 4, 128>>>(edge_attrs, edge_embedding, edge_index,
                                          W_fc1, W_fc2, E, N);

    // --- output ---
    out_kernel<<<(N + 15) / 16, 256>>>(W_lin2_0, W_lin2_1, out, N);
}

// round 12
// speedup vs baseline: 1.3556x; 1.1851x over previous
#include <cuda_runtime.h>
#include <cuda_bf16.h>
#include <math.h>

// Problem constants (fixed shapes per reference)
#define NN_MAX 10000
#define EE_MAX 320000
#define C 64

static __device__ float g_ypack[NN_MAX * 256]; // [n][u][4] : {y0, y1x, y1y, y1z}
static __device__ float g_sc0[NN_MAX * 64];    // [n][v]
static __device__ float g_sc1[NN_MAX * 192];   // [n][m][v]
static __device__ float g_agg[NN_MAX * 512];   // [n][u][8] : {s0,s1,v00,v01,v02,v10,v11,v12}

// CSR sort scratch + sorted edge payload
static __device__ int    g_count [NN_MAX];       // per-dst edge count
static __device__ int    g_offset[NN_MAX + 1];   // exclusive prefix
static __device__ int    g_cursor[NN_MAX];       // scatter cursors
static __device__ int    g_src_s [EE_MAX];       // src id, dst-sorted order
static __device__ float4 g_edat  [EE_MAX * 3];   // per sorted edge: {sh0,sh1x,sh1y,sh1z},{h0..h3},{h4..h7}

#define INV_SQRT_C    0.125f            // 1/sqrt(64)
#define SC_NORM       0.0625f           // 1/sqrt(64*4)
#define INV_SQRT_NB   0.3535533905932738f  // 1/sqrt(8)
#define INV_SQRT_H    0.3535533905932738f
#define INV_SQRT3     0.5773502691896258f
#define K_SCALE       0.015625f         // 1/(sqrt(32)*sqrt(128)) = 1/64
#define LOG2F_        0.6931471805599453f

// softplus(x) - log(2), numerically stable
static __device__ __forceinline__ float ssp_m_log2(float x) {
    return fmaxf(x, 0.f) + log1pf(expf(-fabsf(x))) - LOG2F_;
}

// ---------------------------------------------------------------------------
// Sort kernel A: zero the per-dst counters
// ---------------------------------------------------------------------------
__global__ void zero_count_kernel(int N) {
    int i = blockIdx.x * blockDim.x + threadIdx.x;
    if (i < N) g_count[i] = 0;
}

// ---------------------------------------------------------------------------
// Sort kernel B: histogram of dst
// ---------------------------------------------------------------------------
__global__ void hist_kernel(const int* __restrict__ eidx, int E) {
    int e = blockIdx.x * blockDim.x + threadIdx.x;
    if (e < E) atomicAdd(&g_count[eidx[e]], 1);
}

// ---------------------------------------------------------------------------
// Sort kernel C: single-block exclusive scan over N counts (N <= 10240)
// ---------------------------------------------------------------------------
__global__ __launch_bounds__(1024) void scan_kernel(int N) {
    __shared__ int ssum[1024];
    const int tid = threadIdx.x;
    const int per = (N + 1023) / 1024;
    const int base = tid * per;

    int s = 0;
    for (int j = 0; j < per; j++) {
        int idx = base + j;
        if (idx < N) s += g_count[idx];
    }
    ssum[tid] = s;
    __syncthreads();
    // Hillis-Steele inclusive scan
    for (int off = 1; off < 1024; off <<= 1) {
        int v = (tid >= off) ? ssum[tid - off] : 0;
        __syncthreads();
        ssum[tid] += v;
        __syncthreads();
    }
    int run = (tid == 0) ? 0 : ssum[tid - 1];
    for (int j = 0; j < per; j++) {
        int idx = base + j;
        if (idx < N) {
            g_offset[idx] = run;
            g_cursor[idx] = run;
            run += g_count[idx];
        }
    }
    if (tid == 1023) g_offset[N] = ssum[1023];
}

// ---------------------------------------------------------------------------
// Sort kernel D: scatter edge payload into dst-sorted order.
//   Also computes the radial MLP hidden h[8] = ssp(emb @ Wfc1 / sqrt(NB)).
//   Reads are coalesced (edge order); writes are scattered stores (latency-free).
// ---------------------------------------------------------------------------
__global__ __launch_bounds__(256) void scatter_kernel(
    const int*   __restrict__ eidx,   // [2,E]
    const float* __restrict__ eattr,  // [E,4]
    const float* __restrict__ eemb,   // [E,8]
    const float* __restrict__ Wfc1,   // [8,8]
    int E)
{
    __shared__ float sW[64];
    const int tid = threadIdx.x;
    if (tid < 64) sW[tid] = Wfc1[tid] * INV_SQRT_NB;
    __syncthreads();

    int e = blockIdx.x * blockDim.x + tid;
    if (e >= E) return;

    const int d   = eidx[e];
    const int src = eidx[E + e];
    const int pos = atomicAdd(&g_cursor[d], 1);

    const float4 ea = *reinterpret_cast<const float4*>(eattr + (size_t)e * 4);
    const float4 m0 = *reinterpret_cast<const float4*>(eemb + (size_t)e * 8);
    const float4 m1 = *reinterpret_cast<const float4*>(eemb + (size_t)e * 8 + 4);
    const float emb[8] = {m0.x, m0.y, m0.z, m0.w, m1.x, m1.y, m1.z, m1.w};

    float h[8];
    #pragma unroll
    for (int k = 0; k < 8; k++) {
        float acc = 0.f;
        #pragma unroll
        for (int b = 0; b < 8; b++) acc += emb[b] * sW[b * 8 + k];
        h[k] = ssp_m_log2(acc);
    }

    g_src_s[pos] = src;
    float4* ed = g_edat + (size_t)pos * 3;
    ed[0] = ea;
    ed[1] = make_float4(h[0], h[1], h[2], h[3]);
    ed[2] = make_float4(h[4], h[5], h[6], h[7]);
}

// ---------------------------------------------------------------------------
// Kernel 1: per-node precompute  y (packed), sc0, sc1
//   block = 64 threads (thread = output channel v), 8 nodes per block
// ---------------------------------------------------------------------------
__global__ __launch_bounds__(64) void node_kernel(
    const float* __restrict__ nf,     // [N,256]
    const float* __restrict__ attrs,  // [N,4]
    const float* __restrict__ Wl0,    // [64,64]
    const float* __restrict__ Wl1,    // [64,64]
    const float* __restrict__ Wsc0,   // [64,4,64]
    const float* __restrict__ Wsc1,   // [64,4,64]
    int N)
{
    __shared__ float sx0[8][64];
    __shared__ float sx1[8][3][64];
    __shared__ float sat[8][4];

    const int v  = threadIdx.x;
    const int n0 = blockIdx.x * 8;
    const int nn = min(8, N - n0);

    for (int i = 0; i < nn; i++) {
        const float* row = nf + (size_t)(n0 + i) * 256;
        sx0[i][v] = row[v];
        #pragma unroll
        for (int j = 0; j < 3; j++) {
            int c = v + j * 64;          // flat (u,m) index, u=c/3 m=c%3
            sx1[i][c % 3][c / 3] = row[64 + c];
        }
    }
    if (v < 32) {
        int i = v >> 2, a = v & 3;
        if (i < nn) sat[i][a] = attrs[(size_t)(n0 + i) * 4 + a];
    }
    __syncthreads();

    float y0[8], y1[8][3], s0[8], s1[8][3];
    #pragma unroll
    for (int i = 0; i < 8; i++) {
        y0[i] = 0.f; s0[i] = 0.f;
        #pragma unroll
        for (int m = 0; m < 3; m++) { y1[i][m] = 0.f; s1[i][m] = 0.f; }
    }

    for (int u = 0; u < 64; u++) {
        float wl0 = Wl0[u * 64 + v];
        float wl1 = Wl1[u * 64 + v];
        float w0a[4], w1a[4];
        #pragma unroll
        for (int a = 0; a < 4; a++) {
            w0a[a] = Wsc0[(u * 4 + a) * 64 + v];
            w1a[a] = Wsc1[(u * 4 + a) * 64 + v];
        }
        #pragma unroll
        for (int i = 0; i < 8; i++) {
            float a0 = sat[i][0], a1 = sat[i][1], a2 = sat[i][2], a3 = sat[i][3];
            float gg0 = a0 * w0a[0] + a1 * w0a[1] + a2 * w0a[2] + a3 * w0a[3];
            float gg1 = a0 * w1a[0] + a1 * w1a[1] + a2 * w1a[2] + a3 * w1a[3];
            float x0 = sx0[i][u];
            y0[i] += x0 * wl0;
            s0[i] += x0 * gg0;
            #pragma unroll
            for (int m = 0; m < 3; m++) {
                float xm = sx1[i][m][u];
                y1[i][m] += xm * wl1;
                s1[i][m] += xm * gg1;
            }
        }
    }

    for (int i = 0; i < nn; i++) {
        int n = n0 + i;
        float4 yv = make_float4(y0[i] * INV_SQRT_C,
                                y1[i][0] * INV_SQRT_C,
                                y1[i][1] * INV_SQRT_C,
                                y1[i][2] * INV_SQRT_C);
        *reinterpret_cast<float4*>(g_ypack + (size_t)n * 256 + v * 4) = yv;
        g_sc0[(size_t)n * 64 + v] = s0[i] * SC_NORM;
        #pragma unroll
        for (int m = 0; m < 3; m++)
            g_sc1[(size_t)n * 192 + m * 64 + v] = s1[i][m] * SC_NORM;
    }
}

// ---------------------------------------------------------------------------
// Kernel 2: CSR edge aggregation — one warp per dst node, NO atomics.
//   Per edge: 3 uniform-broadcast LDG.128 (sorted payload), 1 sequential src,
//   2 random ypack LDG.128. Pure FMA afterwards (no shfl / MUFU in loop).
// ---------------------------------------------------------------------------
__global__ __launch_bounds__(128) void edge_csr_kernel(
    const float* __restrict__ Wfc2,   // [8,256]
    int N)
{
    const int tid  = threadIdx.x;
    const int lane = tid & 31;

    // register-cache W_fc2: columns {u0, 64+u0, 128+u0, 192+u0, u1, 64+u1, 128+u1, 192+u1}
    float W2[8][8];
    {
        const int u0 = lane, u1 = lane + 32;
        int jc[8];
        jc[0] = u0; jc[1] = 64 + u0; jc[2] = 128 + u0; jc[3] = 192 + u0;
        jc[4] = u1; jc[5] = 64 + u1; jc[6] = 128 + u1; jc[7] = 192 + u1;
        #pragma unroll
        for (int k = 0; k < 8; k++)
            #pragma unroll
            for (int c = 0; c < 8; c++)
                W2[k][c] = Wfc2[k * 256 + jc[c]] * INV_SQRT_H;
    }

    const int node = blockIdx.x * 4 + (tid >> 5);
    if (node >= N) return;

    const int start = g_offset[node];
    const int end   = g_offset[node + 1];

    float acc[2][8];
    #pragma unroll
    for (int h2 = 0; h2 < 2; h2++)
        #pragma unroll
        for (int c = 0; c < 8; c++) acc[h2][c] = 0.f;

    // prefetch first src
    int src_nxt = (start < end) ? g_src_s[start] : 0;

    for (int i = start; i < end; i++) {
        const int src = src_nxt;
        if (i + 1 < end) src_nxt = g_src_s[i + 1];

        const float4* ed = g_edat + (size_t)i * 3;
        const float4 d0 = ed[0];   // {sh0, sh1x, sh1y, sh1z}
        const float4 d1 = ed[1];   // {h0..h3}
        const float4 d2 = ed[2];   // {h4..h7}
        const float sh0  = d0.x;
        const float sh1x = d0.y;
        const float sh1y = d0.z;
        const float sh1z = d0.w;
        const float h[8] = {d1.x, d1.y, d1.z, d1.w, d2.x, d2.y, d2.z, d2.w};

        // w columns this lane needs (wp1..wp4 for its two channels)
        float w[8];
        #pragma unroll
        for (int c = 0; c < 8; c++) {
            float a2 = 0.f;
            #pragma unroll
            for (int k = 0; k < 8; k++) a2 += h[k] * W2[k][c];
            w[c] = a2;
        }

        const float* yp = g_ypack + (size_t)src * 256;

        #pragma unroll
        for (int half = 0; half < 2; half++) {
            const int u = lane + half * 32;
            const float4 y = *reinterpret_cast<const float4*>(yp + u * 4);
            const float x0  = y.x;
            const float x1x = y.y;
            const float x1y = y.z;
            const float x1z = y.w;
            const float wp1 = w[half * 4 + 0];
            const float wp2 = w[half * 4 + 1];
            const float wp3 = w[half * 4 + 2];
            const float wp4 = w[half * 4 + 3];

            const float dot3 = x1x * sh1x + x1y * sh1y + x1z * sh1z;
            acc[half][0] += wp1 * x0 * sh0;                  // s0
            acc[half][1] += wp4 * dot3 * INV_SQRT3;          // s1
            const float a = wp2 * x0;
            acc[half][2] += a * sh1x;                        // v00
            acc[half][3] += a * sh1y;                        // v01
            acc[half][4] += a * sh1z;                        // v02
            const float b = wp3 * sh0;
            acc[half][5] += b * x1x;                         // v10
            acc[half][6] += b * x1y;                         // v11
            acc[half][7] += b * x1z;                         // v12
        }
    }

    // write agg row once (plain stores — every node covered by exactly one warp)
    float* aggp = g_agg + (size_t)node * 512;
    #pragma unroll
    for (int half = 0; half < 2; half++) {
        const int u = lane + half * 32;
        float4 w0 = make_float4(acc[half][0], acc[half][1], acc[half][2], acc[half][3]);
        float4 w1 = make_float4(acc[half][4], acc[half][5], acc[half][6], acc[half][7]);
        *reinterpret_cast<float4*>(aggp + u * 8)     = w0;
        *reinterpret_cast<float4*>(aggp + u * 8 + 4) = w1;
    }
}

// ---------------------------------------------------------------------------
// Kernel 3: output linears + shortcut
//   block = 256 threads, 16 nodes per block, 4 nodes per thread
// ---------------------------------------------------------------------------
__global__ __launch_bounds__(256) void out_kernel(
    const float* __restrict__ Wl20,   // [128,64]
    const float* __restrict__ Wl21,   // [128,64]
    float* __restrict__ out,          // [N,256]
    int N)
{
    __shared__ float sagg[16][512];
    const int tid = threadIdx.x;
    const int ni  = tid >> 6;
    const int v   = tid & 63;
    const int n0  = blockIdx.x * 16;

    // stage up to 16 nodes of agg (128 float4 per node)
    {
        const float4* srcp = reinterpret_cast<const float4*>(g_agg + (size_t)n0 * 512);
        float4* dstp = reinterpret_cast<float4*>(&sagg[0][0]);
        const int avail = min(16, N - n0) * 128;
        for (int i = tid; i < avail; i += 256)
            dstp[i] = srcp[i];
    }
    __syncthreads();

    float acc0[4], acc1[4][3];
    #pragma unroll
    for (int j = 0; j < 4; j++) {
        const int n = n0 + ni + 4 * j;
        if (n < N) {
            acc0[j] = g_sc0[(size_t)n * 64 + v];
            #pragma unroll
            for (int m = 0; m < 3; m++)
                acc1[j][m] = g_sc1[(size_t)n * 192 + m * 64 + v];
        } else {
            acc0[j] = 0.f;
            #pragma unroll
            for (int m = 0; m < 3; m++) acc1[j][m] = 0.f;
        }
    }

    #pragma unroll 2
    for (int u = 0; u < 64; u++) {
        const float waL = Wl20[u * 64 + v]        * K_SCALE;   // U = u
        const float waH = Wl20[(64 + u) * 64 + v] * K_SCALE;   // U = 64+u
        const float wbL = Wl21[u * 64 + v]        * K_SCALE;
        const float wbH = Wl21[(64 + u) * 64 + v] * K_SCALE;
        #pragma unroll
        for (int j = 0; j < 4; j++) {
            const float* g = &sagg[ni + 4 * j][u * 8];
            const float4 gA = *reinterpret_cast<const float4*>(g);     // {s0,s1,v00,v01}
            const float4 gB = *reinterpret_cast<const float4*>(g + 4); // {v02,v10,v11,v12}
            acc0[j]    += gA.x * waL + gA.y * waH;
            acc1[j][0] += gA.z * wbL + gB.y * wbH;
            acc1[j][1] += gA.w * wbL + gB.z * wbH;
            acc1[j][2] += gB.x * wbL + gB.w * wbH;
        }
    }

    #pragma unroll
    for (int j = 0; j < 4; j++) {
        const int n = n0 + ni + 4 * j;
        if (n < N) {
            float* orow = out + (size_t)n * 256;
            orow[v] = acc0[j];
            #pragma unroll
            for (int m = 0; m < 3; m++)
                orow[64 + v * 3 + m] = acc1[j][m];
        }
    }
}

// ---------------------------------------------------------------------------
extern "C" void kernel_launch(void* const* d_in, const int* in_sizes, int n_in,
                              void* d_out, int out_size)
{
    const float* node_features  = (const float*)d_in[0];
    const float* node_attrs     = (const float*)d_in[1];
    const float* edge_attrs     = (const float*)d_in[2];
    const float* edge_embedding = (const float*)d_in[3];
    const int*   edge_index     = (const int*)  d_in[4];
    const float* W_lin1_0       = (const float*)d_in[5];
    const float* W_lin1_1       = (const float*)d_in[6];
    const float* W_fc1          = (const float*)d_in[7];
    const float* W_fc2          = (const float*)d_in[8];
    const float* W_lin2_0       = (const float*)d_in[9];
    const float* W_lin2_1       = (const float*)d_in[10];
    const float* W_sc0          = (const float*)d_in[11];
    const float* W_sc1          = (const float*)d_in[12];
    float* out = (float*)d_out;

    const int N = in_sizes[0] / 256;
    const int E = in_sizes[2] / 4;

    // --- CSR sort of edges by dst (+ radial MLP hidden h precompute) ---
    zero_count_kernel<<<(N + 255) / 256, 256>>>(N);
    hist_kernel<<<(E + 255) / 256, 256>>>(edge_index, E);
    scan_kernel<<<1, 1024>>>(N);
    scatter_kernel<<<(E + 255) / 256, 256>>>(edge_index, edge_attrs,
                                             edge_embedding, W_fc1, E);

    // --- node precompute (independent of sort) ---
    node_kernel<<<(N + 7) / 8, 64>>>(node_features, node_attrs,
                                     W_lin1_0, W_lin1_1, W_sc0, W_sc1, N);

    // --- edge aggregation, warp per node, no atomics ---
    edge_csr_kernel<<<(N + 3) / 4, 128>>>(W_fc2, N);

    // --- output ---
    out_kernel<<<(N + 15) / 16, 256>>>(W_lin2_0, W_lin2_1, out, N);
}